// round 2
// baseline (speedup 1.0000x reference)
#include <cuda_runtime.h>
#include <math_constants.h>

#define HH 224
#define WW 224
#define HWP (HH * WW)      // 50176
#define BB 64
#define RBLK 16            // reduce blocks per batch

// Per-(batch, block) partial min/max. Plain stores -> no init kernel, no
// atomics; deterministic across graph replays.
__device__ float g_pmax[BB][RBLK];
__device__ float g_pmin[BB][RBLK];

__global__ void __launch_bounds__(256)
reduce_kernel(const float* __restrict__ depth, const float* __restrict__ obj) {
    const int b = blockIdx.y;
    const float4* dp = reinterpret_cast<const float4*>(depth + (size_t)b * HWP);
    const float4* op = reinterpret_cast<const float4*>(obj + (size_t)b * HWP);
    float mx = -CUDART_INF_F, mn = CUDART_INF_F;
    const int n4 = HWP / 4;  // 12544
    // 12544 / (16*256) = 3.0625 iterations; grid-stride.
    for (int i = blockIdx.x * blockDim.x + threadIdx.x; i < n4;
         i += RBLK * 256) {
        float4 d = dp[i];
        float4 o = op[i];
        float p0 = d.x * o.x, p1 = d.y * o.y, p2 = d.z * o.z, p3 = d.w * o.w;
        mx = fmaxf(mx, fmaxf(fmaxf(p0, p1), fmaxf(p2, p3)));
        mn = fminf(mn, fminf(fminf(p0, p1), fminf(p2, p3)));
    }
#pragma unroll
    for (int off = 16; off; off >>= 1) {
        mx = fmaxf(mx, __shfl_xor_sync(0xffffffffu, mx, off));
        mn = fminf(mn, __shfl_xor_sync(0xffffffffu, mn, off));
    }
    __shared__ float smx[8], smn[8];
    int w = threadIdx.x >> 5, l = threadIdx.x & 31;
    if (l == 0) { smx[w] = mx; smn[w] = mn; }
    __syncthreads();
    if (threadIdx.x == 0) {
#pragma unroll
        for (int i = 1; i < 8; i++) {
            mx = fmaxf(mx, smx[i]);
            mn = fminf(mn, smn[i]);
        }
        g_pmax[b][blockIdx.x] = mx;
        g_pmin[b][blockIdx.x] = mn;
    }
}

// One float4 (4 consecutive w-pixels, same row) per thread.
// gridDim.x = 64 batches * 49 blocks, blockDim = 256 (256*4 = 1024 px/block,
// 49*1024 = 50176 = HW exactly).
__global__ void __launch_bounds__(256)
main_kernel(const float* __restrict__ depth, const float* __restrict__ obj,
            const float* __restrict__ gaze, const long long* __restrict__ hp,
            float* __restrict__ out) {
    const int b  = blockIdx.x / 49;
    const int lb = blockIdx.x % 49;

    __shared__ float s_pd, s_fr, s_hp0f, s_hp1f, s_gx, s_gy, s_rn2;
    if (threadIdx.x < 32) {
        // Lanes 0..15 fetch partials, shfl-reduce, lane 0 computes scalars.
        float mx = (threadIdx.x < RBLK) ? g_pmax[b][threadIdx.x] : -CUDART_INF_F;
        float mn = (threadIdx.x < RBLK) ? g_pmin[b][threadIdx.x] :  CUDART_INF_F;
#pragma unroll
        for (int off = 8; off; off >>= 1) {
            mx = fmaxf(mx, __shfl_xor_sync(0xffffffffu, mx, off));
            mn = fminf(mn, __shfl_xor_sync(0xffffffffu, mn, off));
        }
        if (threadIdx.x == 0) {
            int hp0 = (int)hp[2 * b];
            int hp1 = (int)hp[2 * b + 1];
            size_t hidx = (size_t)b * HWP + (size_t)hp0 * WW + hp1;
            float hd = depth[hidx] * obj[hidx];
            float gx = gaze[3 * b], gy = gaze[3 * b + 1], gz = gaze[3 * b + 2];
            s_pd = hd + gz * 224.0f;
            s_fr = (mx - mn) / 24.0f;
            s_hp0f = (float)hp0;
            s_hp1f = (float)hp1;
            s_gx = gx;
            s_gy = gy;
            s_rn2 = gx * gx + gy * gy;
        }
    }
    __syncthreads();

    const int idx = lb * 256 + threadIdx.x;  // float4 index within image
    const int pix = idx * 4;
    const int h  = pix / WW;
    const int w0 = pix % WW;  // 4 consecutive pixels stay in one row (224 % 4 == 0)

    const float4 d4 = *reinterpret_cast<const float4*>(depth + (size_t)b * HWP + pix);
    const float4 o4 = *reinterpret_cast<const float4*>(obj   + (size_t)b * HWP + pix);

    const float pd = s_pd, fr = s_fr;
    const float lo1 = pd - fr,        hi1 = pd + fr;
    const float lo2 = pd - 2.f * fr,  hi2 = pd + 2.f * fr;
    const float lo3 = pd - 3.f * fr,  hi3 = pd + 3.f * fr;
    const float a1  = (float)h - s_hp1f;
    const float gx = s_gx, gy = s_gy, rn2 = s_rn2;
    const float c2 = 0.9330127018922193f;           // cos^2(pi/12)
    const float angscale = 12.0f / CUDART_PI_F;

    float dv[4] = {d4.x * o4.x, d4.y * o4.y, d4.z * o4.z, d4.w * o4.w};
    float ov[3][4];

#pragma unroll
    for (int j = 0; j < 4; j++) {
        float a0 = (float)(w0 + j) - s_hp0f;
        float dot = a0 * gx + a1 * gy;
        float an2 = a0 * a0 + a1 * a1;
        float mask = 0.f;
        float t = an2 * rn2;
        // Inside the 15-degree cone iff dot>0 and dot^2 > cos^2(15deg)*t.
        // Degenerate cases (t==0 -> dot==0) and jax NaN->0 fall out as mask=0.
        if (dot > 0.f && dot * dot > c2 * t) {
            float r = dot * rsqrtf(t);
            // r > 1 (fp noise) -> acosf NaN -> fmaxf scrubs to 0, matching
            // jnp.nan_to_num(jnp.maximum(...)).
            mask = fmaxf(1.0f - angscale * acosf(r), 0.0f);
        }
        float d = dv[j];
        float v = d * mask;
        ov[0][j] = (lo1 <= d && hi1 >= d) ? v : 0.f;
        ov[1][j] = (lo2 <= d && hi2 >= d) ? v : 0.f;
        ov[2][j] = (lo3 <= d && hi3 >= d) ? v : 0.f;
    }

    size_t obase = (size_t)b * 3 * HWP + pix;
    *reinterpret_cast<float4*>(out + obase)           = make_float4(ov[0][0], ov[0][1], ov[0][2], ov[0][3]);
    *reinterpret_cast<float4*>(out + obase + HWP)     = make_float4(ov[1][0], ov[1][1], ov[1][2], ov[1][3]);
    *reinterpret_cast<float4*>(out + obase + 2 * HWP) = make_float4(ov[2][0], ov[2][1], ov[2][2], ov[2][3]);
}

extern "C" void kernel_launch(void* const* d_in, const int* in_sizes, int n_in,
                              void* d_out, int out_size) {
    const float* depth = (const float*)d_in[0];
    const float* obj   = (const float*)d_in[1];
    const float* gaze  = (const float*)d_in[2];
    const long long* hp = (const long long*)d_in[3];
    float* out = (float*)d_out;

    reduce_kernel<<<dim3(RBLK, BB), 256>>>(depth, obj);
    main_kernel<<<BB * 49, 256>>>(depth, obj, gaze, hp, out);
}